// round 13
// baseline (speedup 1.0000x reference)
#include <cuda_runtime.h>
#include <cuda_fp16.h>
#include <cstdint>

#define Ndim 1024
#define Mdim 1024
#define Tdim 64
#define Ddim 128

#define BN 64
#define BM 64
#define BT 2
#define MTILES (Mdim / BM)     // 16
#define KC 64                  // halves per B chunk
#define NCHUNK 2               // B chunks per m-tile
#define NG (MTILES * NCHUNK)   // 32 global chunk iterations
#define PADA 136               // A row stride in halves (272B = 68 words, conflict-free)
#define PADB 72                // B row stride in halves (144B = 36 words, conflict-free)
#define THREADS 128

#define A_BYTES  (BT * BN * PADA * 2)     // 34816
#define B_STAGE  (BT * BM * PADB * 2)     // 18432
#define B_BYTES  (2 * B_STAGE)            // 36864
#define EPI_BYTES (BT * BN * 66 * 4)      // 33792
#define OFF_A 0
#define OFF_B A_BYTES
#define OFF_EPI (A_BYTES + B_BYTES)
#define SMEM_TOTAL (A_BYTES + B_BYTES + EPI_BYTES)   // 105472 -> 2 CTAs/SM
#define EPI_T_STRIDE (BN * 66)

__device__ float  g_s1[Ndim * Tdim];
__device__ float  g_s2[Mdim * Tdim];
__device__ __half g_h1[(size_t)Ndim * Tdim * Ddim];
__device__ __half g_h2[(size_t)Mdim * Tdim * Ddim];

// ---------------- helpers ----------------
__device__ __forceinline__ uint32_t smem_u32(const void* p) {
    uint32_t a;
    asm("{ .reg .u64 t; cvta.to.shared.u64 t, %1; cvt.u32.u64 %0, t; }" : "=r"(a) : "l"(p));
    return a;
}
__device__ __forceinline__ void cp_async16(uint32_t dst, const void* src) {
    asm volatile("cp.async.cg.shared.global [%0], [%1], 16;" :: "r"(dst), "l"(src));
}
__device__ __forceinline__ void cp_commit() {
    asm volatile("cp.async.commit_group;" ::: "memory");
}
template <int N>
__device__ __forceinline__ void cp_wait() {
    asm volatile("cp.async.wait_group %0;" :: "n"(N) : "memory");
}

__device__ __forceinline__ void mma16816(float* c, uint32_t a0, uint32_t a1,
                                         uint32_t a2, uint32_t a3,
                                         uint32_t b0, uint32_t b1) {
    asm volatile(
        "mma.sync.aligned.m16n8k16.row.col.f32.f16.f16.f32 "
        "{%0,%1,%2,%3}, {%4,%5,%6,%7}, {%8,%9}, {%0,%1,%2,%3};\n"
        : "+f"(c[0]), "+f"(c[1]), "+f"(c[2]), "+f"(c[3])
        : "r"(a0), "r"(a1), "r"(a2), "r"(a3), "r"(b0), "r"(b1));
}

// ---------------------------------------------------------------------------
// Kernel 1: fused fp16 convert + squared row norms. One warp per (row, t).
// ---------------------------------------------------------------------------
__global__ void prep_kernel(const float* __restrict__ X1,
                            const float* __restrict__ X2) {
    int gwarp = (blockIdx.x * blockDim.x + threadIdx.x) >> 5;
    int lane  = threadIdx.x & 31;
    const float* src;
    float* ndst;
    __half* hdst;
    int row;
    if (gwarp < Ndim * Tdim) { src = X1; ndst = g_s1; hdst = g_h1; row = gwarp; }
    else                     { src = X2; ndst = g_s2; hdst = g_h2; row = gwarp - Ndim * Tdim; }
    const float4 v = *((const float4*)(src + (size_t)row * Ddim) + lane);
    __half2 h01 = __floats2half2_rn(v.x, v.y);
    __half2 h23 = __floats2half2_rn(v.z, v.w);
    uint2 packed;
    packed.x = *(uint32_t*)&h01;
    packed.y = *(uint32_t*)&h23;
    *(uint2*)(hdst + (size_t)row * Ddim + lane * 4) = packed;
    float s = v.x * v.x + v.y * v.y + v.z * v.z + v.w * v.w;
    #pragma unroll
    for (int o = 16; o > 0; o >>= 1) s += __shfl_down_sync(0xffffffffu, s, o);
    if (lane == 0) ndst[row] = s;
}

// ---------------------------------------------------------------------------
// Kernel 2: persistent-m batched cross-GEMM.
// CTA owns (64n x 2t) with A (full K) RESIDENT in smem; loops over all 16
// m-tiles with double-buffered B (KC=64 -> 32 chunk iterations).
// 128 threads = 4 warps = 2 t-planes x 2 m-halves; warp tile 64n x 32m.
// Per-m-tile epilogue overlaps the next B chunk's cp.async.
// Grid: (t-tiles, n-tiles), t fastest -> 8B writes merge into sectors in L2.
// ---------------------------------------------------------------------------
__global__ __launch_bounds__(THREADS, 2)
void cross_mma_kernel(float* __restrict__ Y) {
    extern __shared__ char smem[];
    const uint32_t sbase = smem_u32(smem);

    const int tid  = threadIdx.x;
    const int lane = tid & 31;
    const int wid  = tid >> 5;
    const int tp   = wid >> 1;   // t-plane 0..1
    const int mh   = wid & 1;    // m-half 0..1

    const int t0 = blockIdx.x * BT;
    const int n0 = blockIdx.y * BN;

    const int lr = lane >> 2;          // 0..7
    const int lc = (lane & 3) * 2;     // 0,2,4,6
    const int tt = t0 + tp;

    // ---- prologue: load resident A (full K), first B chunk, s1 norms ----
    // A: 2t x 64n x 128k halves = 2048 float4 ; 16 per thread
    #pragma unroll
    for (int it = 0; it < 16; ++it) {
        int i = tid + it * THREADS;        // 0..2047
        int k4 = i & 15, n = (i >> 4) & 63, t = i >> 10;
        const __half* g = g_h1 + ((size_t)(n0 + n) * Tdim + (t0 + t)) * Ddim + k4 * 8;
        cp_async16(sbase + OFF_A + (t * BN + n) * (PADA * 2) + k4 * 16, g);
    }
    // B chunk 0 (m-tile 0, k 0..63) into buf 0, same commit group as A
    auto load_B = [&](int g, int buf) {
        const int j = g >> 1;                  // m-tile
        const int h = g & 1;                   // K half
        const uint32_t bbase = sbase + OFF_B + buf * B_STAGE;
        #pragma unroll
        for (int it = 0; it < 8; ++it) {
            int i = tid + it * THREADS;        // 0..1023
            int k4 = i & 7, m = (i >> 3) & 63, t = i >> 9;
            const __half* gp = g_h2 + ((size_t)(j * BM + m) * Tdim + (t0 + t)) * Ddim
                               + h * KC + k4 * 8;
            cp_async16(bbase + (t * BM + m) * (PADB * 2) + k4 * 16, gp);
        }
        cp_commit();
    };
    load_B(0, 0);    // commits group0 = {A, B0}

    float s1a[4], s1b[4];
    #pragma unroll
    for (int ni = 0; ni < 4; ++ni) {
        s1a[ni] = __ldg(&g_s1[(n0 + ni * 16 + lr) * Tdim + tt]);
        s1b[ni] = __ldg(&g_s1[(n0 + ni * 16 + lr + 8) * Tdim + tt]);
    }

    const float invD = 1.0f / (float)Ddim;
    float acc[4][4][4];
    float s2a[4], s2b[4];
    float* stage = (float*)(smem + OFF_EPI);

    for (int g = 0; g < NG; ++g) {
        const int j = g >> 1;         // m-tile
        const int h = g & 1;          // K half

        if (h == 0) {
            // reset accumulators for the new m-tile; prefetch its s2 norms
            #pragma unroll
            for (int i = 0; i < 4; ++i)
                #pragma unroll
                for (int jj = 0; jj < 4; ++jj)
                    #pragma unroll
                    for (int q = 0; q < 4; ++q) acc[i][jj][q] = 0.0f;
            #pragma unroll
            for (int mi = 0; mi < 4; ++mi) {
                int mg = j * BM + mh * 32 + mi * 8 + lc;
                s2a[mi] = __ldg(&g_s2[mg * Tdim + tt]);
                s2b[mi] = __ldg(&g_s2[(mg + 1) * Tdim + tt]);
            }
        }

        if (g + 1 < NG) {
            load_B(g + 1, (g + 1) & 1);
            cp_wait<1>();    // oldest group (= chunk g) complete
        } else {
            cp_wait<0>();
        }
        __syncthreads();     // chunk g visible; prev buf fully consumed

        const __half* Ah = (const __half*)(smem + OFF_A) + tp * (BN * PADA);
        const __half* Bh = (const __half*)(smem + OFF_B + (g & 1) * B_STAGE)
                           + tp * (BM * PADB);

        #pragma unroll
        for (int s = 0; s < 4; ++s) {        // four k16 steps per 64-chunk
            const int kba = h * KC + s * 16; // within resident A row
            const int kbb = s * 16;          // within B stage row
            uint32_t b0[4], b1[4];
            #pragma unroll
            for (int mi = 0; mi < 4; ++mi) {
                const __half* bp = Bh + (mh * 32 + mi * 8 + lr) * PADB + kbb + lc;
                b0[mi] = *(const uint32_t*)(bp);
                b1[mi] = *(const uint32_t*)(bp + 8);
            }
            #pragma unroll
            for (int ni = 0; ni < 4; ++ni) {
                const __half* ap = Ah + (ni * 16 + lr) * PADA + kba + lc;
                uint32_t a0 = *(const uint32_t*)(ap);
                uint32_t a1 = *(const uint32_t*)(ap + 8 * PADA);
                uint32_t a2 = *(const uint32_t*)(ap + 8);
                uint32_t a3 = *(const uint32_t*)(ap + 8 * PADA + 8);
                #pragma unroll
                for (int mi = 0; mi < 4; ++mi)
                    mma16816(acc[ni][mi], a0, a1, a2, a3, b0[mi], b1[mi]);
            }
        }
        __syncthreads();     // all warps done with this B buf before overwrite

        if (h == 1) {
            // ---- epilogue for m-tile j (overlaps B load of m-tile j+1) ----
            float* plane = stage + tp * EPI_T_STRIDE;
            #pragma unroll
            for (int ni = 0; ni < 4; ++ni) {
                #pragma unroll
                for (int mi = 0; mi < 4; ++mi) {
                    int r  = ni * 16 + lr;
                    int m2 = mh * 32 + mi * 8 + lc;
                    float2 v0, v1;
                    v0.x = (s1a[ni] + s2a[mi] - 2.0f * acc[ni][mi][0]) * invD;
                    v0.y = (s1a[ni] + s2b[mi] - 2.0f * acc[ni][mi][1]) * invD;
                    v1.x = (s1b[ni] + s2a[mi] - 2.0f * acc[ni][mi][2]) * invD;
                    v1.y = (s1b[ni] + s2b[mi] - 2.0f * acc[ni][mi][3]) * invD;
                    *(float2*)(plane + r * 66 + m2)       = v0;
                    *(float2*)(plane + (r + 8) * 66 + m2) = v1;
                }
            }
            __syncthreads();
            // writeback: 8B (2 t's) per (n,m); adjacent-t CTAs fill sectors
            const int m0 = j * BM;
            #pragma unroll
            for (int it = 0; it < 32; ++it) {
                int p = tid + it * THREADS;    // 0..4095
                int n = p >> 6;
                int m = p & 63;
                float2 w;
                w.x = stage[0 * EPI_T_STRIDE + n * 66 + m];
                w.y = stage[1 * EPI_T_STRIDE + n * 66 + m];
                size_t off = ((size_t)(n0 + n) * Mdim + (m0 + m)) * Tdim + t0;
                *(float2*)(Y + off) = w;
            }
            // no trailing sync needed: the next epilogue's staging is ordered
            // behind two chunk-level __syncthreads of m-tile j+1
        }
    }
}

// ---------------------------------------------------------------------------
extern "C" void kernel_launch(void* const* d_in, const int* in_sizes, int n_in,
                              void* d_out, int out_size) {
    const float* X1 = (const float*)d_in[0];
    const float* X2 = (const float*)d_in[1];
    float* Y = (float*)d_out;

    int total_warps = 2 * Ndim * Tdim;
    int blocks = (total_warps * 32) / 256;
    prep_kernel<<<blocks, 256>>>(X1, X2);

    cudaFuncSetAttribute(cross_mma_kernel,
                         cudaFuncAttributeMaxDynamicSharedMemorySize, SMEM_TOTAL);
    dim3 grid(Tdim / BT, Ndim / BN);   // 32 t-tiles (fastest) x 16 n-tiles
    cross_mma_kernel<<<grid, THREADS, SMEM_TOTAL>>>(Y);
}

// round 15
// speedup vs baseline: 1.4753x; 1.4753x over previous
#include <cuda_runtime.h>
#include <cuda_fp16.h>
#include <cstdint>

#define Ndim 1024
#define Mdim 1024
#define Tdim 64
#define Ddim 128

#define BN 64
#define BM 64
#define BT 4
#define KC 16             // halves per K chunk
#define NKC (Ddim / KC)   // 8
#define NSTAGE 3
#define PADK 24           // smem row stride in halves (48B: 16B-aligned, conflict-free)
#define THREADS 256

#define A_STAGE (BT * BN * PADK * 2)       // 12288
#define STAGE_BYTES (2 * A_STAGE)          // 24576 (A then B)
#define SMEM_TOTAL (NSTAGE * STAGE_BYTES)  // 73728 >= epilogue overlay 67584
#define STAGE_T_STRIDE (BN * 66)           // floats per t-plane

__device__ float  g_s1[Ndim * Tdim];
__device__ float  g_s2[Mdim * Tdim];
__device__ __half g_h1[(size_t)Ndim * Tdim * Ddim];
__device__ __half g_h2[(size_t)Mdim * Tdim * Ddim];

// ---------------- helpers ----------------
__device__ __forceinline__ uint32_t smem_u32(const void* p) {
    uint32_t a;
    asm("{ .reg .u64 t; cvta.to.shared.u64 t, %1; cvt.u32.u64 %0, t; }" : "=r"(a) : "l"(p));
    return a;
}
__device__ __forceinline__ void cp_async16(uint32_t dst, const void* src) {
    asm volatile("cp.async.cg.shared.global [%0], [%1], 16;" :: "r"(dst), "l"(src));
}
__device__ __forceinline__ void cp_commit() {
    asm volatile("cp.async.commit_group;" ::: "memory");
}
template <int N>
__device__ __forceinline__ void cp_wait() {
    asm volatile("cp.async.wait_group %0;" :: "n"(N) : "memory");
}

// fp16-accumulator MMA: C/D are 2 regs (4 halfs) per 16x8 tile
__device__ __forceinline__ void mma16816h(uint32_t* c, uint32_t a0, uint32_t a1,
                                          uint32_t a2, uint32_t a3,
                                          uint32_t b0, uint32_t b1) {
    asm volatile(
        "mma.sync.aligned.m16n8k16.row.col.f16.f16.f16.f16 "
        "{%0,%1}, {%2,%3,%4,%5}, {%6,%7}, {%0,%1};\n"
        : "+r"(c[0]), "+r"(c[1])
        : "r"(a0), "r"(a1), "r"(a2), "r"(a3), "r"(b0), "r"(b1));
}

// ---------------------------------------------------------------------------
// Kernel 1: fused fp16 convert + squared row norms. One warp per (row, t).
// ---------------------------------------------------------------------------
__global__ void prep_kernel(const float* __restrict__ X1,
                            const float* __restrict__ X2) {
    int gwarp = (blockIdx.x * blockDim.x + threadIdx.x) >> 5;
    int lane  = threadIdx.x & 31;
    const float* src;
    float* ndst;
    __half* hdst;
    int row;
    if (gwarp < Ndim * Tdim) { src = X1; ndst = g_s1; hdst = g_h1; row = gwarp; }
    else                     { src = X2; ndst = g_s2; hdst = g_h2; row = gwarp - Ndim * Tdim; }
    const float4 v = *((const float4*)(src + (size_t)row * Ddim) + lane);
    __half2 h01 = __floats2half2_rn(v.x, v.y);
    __half2 h23 = __floats2half2_rn(v.z, v.w);
    uint2 packed;
    packed.x = *(uint32_t*)&h01;
    packed.y = *(uint32_t*)&h23;
    *(uint2*)(hdst + (size_t)row * Ddim + lane * 4) = packed;
    float s = v.x * v.x + v.y * v.y + v.z * v.z + v.w * v.w;
    #pragma unroll
    for (int o = 16; o > 0; o >>= 1) s += __shfl_down_sync(0xffffffffu, s, o);
    if (lane == 0) ndst[row] = s;
}

// ---------------------------------------------------------------------------
// Kernel 2: batched cross-GEMM via mma.sync, fp16 accumulators.
// CTA: 256 threads = 8 warps = 4 t-planes x 2 m-halves, warp tile 64n x 32m.
// 3 CTAs/SM; 3-stage cp.async pipeline, ONE barrier per K chunk.
// Grid: t fastest so 16B writes of adjacent-t CTAs merge into full sectors.
// ---------------------------------------------------------------------------
__global__ __launch_bounds__(THREADS, 3)
void cross_mma_kernel(float* __restrict__ Y) {
    extern __shared__ char smem[];
    const uint32_t sbase = smem_u32(smem);

    const int tid  = threadIdx.x;
    const int lane = tid & 31;
    const int wid  = tid >> 5;
    const int tp   = wid >> 1;   // t-plane 0..3
    const int mh   = wid & 1;    // m-half 0..1

    const int t0 = blockIdx.x * BT;    // t fastest
    const int m0 = blockIdx.y * BM;
    const int n0 = blockIdx.z * BN;

    const int lr = lane >> 2;          // 0..7
    const int lc = (lane & 3) * 2;     // 0,2,4,6

    uint32_t acc[4][4][2];             // fp16x2 accumulators
    #pragma unroll
    for (int i = 0; i < 4; ++i)
        #pragma unroll
        for (int j = 0; j < 4; ++j) { acc[i][j][0] = 0u; acc[i][j][1] = 0u; }

    // ---- loader: A 512 + B 512 float4 per stage / 256 thr = 4 each ----
    auto load_stage = [&](int cc, int buf) {
        const uint32_t abase = sbase + buf * STAGE_BYTES;
        const uint32_t bbase = abase + A_STAGE;
        #pragma unroll
        for (int it = 0; it < 4; ++it) {
            int i = tid + it * THREADS;          // 0..1023
            if (i < 512) {
                int k4 = i & 1, n = (i >> 1) & 63, t = i >> 7;
                const __half* g = g_h1 + ((size_t)(n0 + n) * Tdim + (t0 + t)) * Ddim
                                  + cc * KC + k4 * 8;
                cp_async16(abase + t * (BN * PADK * 2) + n * (PADK * 2) + k4 * 16, g);
            } else {
                int j = i - 512;
                int k4 = j & 1, m = (j >> 1) & 63, t = j >> 7;
                const __half* g = g_h2 + ((size_t)(m0 + m) * Tdim + (t0 + t)) * Ddim
                                  + cc * KC + k4 * 8;
                cp_async16(bbase + t * (BM * PADK * 2) + m * (PADK * 2) + k4 * 16, g);
            }
        }
        cp_commit();
    };

    load_stage(0, 0);
    load_stage(1, 1);

    for (int cc = 0; cc < NKC; ++cc) {
        if (cc < NKC - 1) cp_wait<1>();    // oldest (= chunk cc) landed
        else              cp_wait<0>();
        __syncthreads();                   // all warps done with chunk cc-1's buf
        if (cc + 2 < NKC) load_stage(cc + 2, (cc + 2) % NSTAGE);

        const int buf = cc % NSTAGE;
        const __half* Ah = (const __half*)(smem + buf * STAGE_BYTES) + tp * (BN * PADK);
        const __half* Bh = (const __half*)(smem + buf * STAGE_BYTES + A_STAGE) + tp * (BM * PADK);

        uint32_t b0[4], b1[4];
        #pragma unroll
        for (int mi = 0; mi < 4; ++mi) {
            const __half* bp = Bh + (mh * 32 + mi * 8 + lr) * PADK + lc;
            b0[mi] = *(const uint32_t*)(bp);
            b1[mi] = *(const uint32_t*)(bp + 8);
        }
        #pragma unroll
        for (int ni = 0; ni < 4; ++ni) {
            const __half* ap = Ah + (ni * 16 + lr) * PADK + lc;
            uint32_t a0 = *(const uint32_t*)(ap);
            uint32_t a1 = *(const uint32_t*)(ap + 8 * PADK);
            uint32_t a2 = *(const uint32_t*)(ap + 8);
            uint32_t a3 = *(const uint32_t*)(ap + 8 * PADK + 8);
            #pragma unroll
            for (int mi = 0; mi < 4; ++mi)
                mma16816h(acc[ni][mi], a0, a1, a2, a3, b0[mi], b1[mi]);
        }
    }
    __syncthreads();      // compute fully done; smem reusable as epilogue stage

    // ---- epilogue: convert, combine with norms, stage [t][n][66] ----
    const float invD = 1.0f / (float)Ddim;
    const int tt = t0 + tp;
    float s1a[4], s1b[4], s2a[4], s2b[4];
    #pragma unroll
    for (int ni = 0; ni < 4; ++ni) {
        s1a[ni] = __ldg(&g_s1[(n0 + ni * 16 + lr) * Tdim + tt]);
        s1b[ni] = __ldg(&g_s1[(n0 + ni * 16 + lr + 8) * Tdim + tt]);
    }
    #pragma unroll
    for (int mi = 0; mi < 4; ++mi) {
        int mg = m0 + mh * 32 + mi * 8 + lc;
        s2a[mi] = __ldg(&g_s2[mg * Tdim + tt]);
        s2b[mi] = __ldg(&g_s2[(mg + 1) * Tdim + tt]);
    }

    float* stage = (float*)smem;
    float* plane = stage + tp * STAGE_T_STRIDE;
    #pragma unroll
    for (int ni = 0; ni < 4; ++ni) {
        #pragma unroll
        for (int mi = 0; mi < 4; ++mi) {
            int r  = ni * 16 + lr;
            int m2 = mh * 32 + mi * 8 + lc;
            float2 lo = __half22float2(*(__half2*)&acc[ni][mi][0]);  // row r
            float2 hi = __half22float2(*(__half2*)&acc[ni][mi][1]);  // row r+8
            float2 v0, v1;
            v0.x = (s1a[ni] + s2a[mi] - 2.0f * lo.x) * invD;
            v0.y = (s1a[ni] + s2b[mi] - 2.0f * lo.y) * invD;
            v1.x = (s1b[ni] + s2a[mi] - 2.0f * hi.x) * invD;
            v1.y = (s1b[ni] + s2b[mi] - 2.0f * hi.y) * invD;
            *(float2*)(plane + r * 66 + m2)       = v0;
            *(float2*)(plane + (r + 8) * 66 + m2) = v1;
        }
    }
    __syncthreads();

    // ---- writeback: full 16B (4 t's) per (n,m) ----
    #pragma unroll
    for (int it = 0; it < 16; ++it) {
        int p = tid + it * THREADS;    // 0..4095
        int n = p >> 6;
        int m = p & 63;
        float4 w;
        w.x = stage[0 * STAGE_T_STRIDE + n * 66 + m];
        w.y = stage[1 * STAGE_T_STRIDE + n * 66 + m];
        w.z = stage[2 * STAGE_T_STRIDE + n * 66 + m];
        w.w = stage[3 * STAGE_T_STRIDE + n * 66 + m];
        size_t off = ((size_t)(n0 + n) * Mdim + (m0 + m)) * Tdim + t0;
        *(float4*)(Y + off) = w;
    }
}

// ---------------------------------------------------------------------------
extern "C" void kernel_launch(void* const* d_in, const int* in_sizes, int n_in,
                              void* d_out, int out_size) {
    const float* X1 = (const float*)d_in[0];
    const float* X2 = (const float*)d_in[1];
    float* Y = (float*)d_out;

    int total_warps = 2 * Ndim * Tdim;
    int blocks = (total_warps * 32) / 256;
    prep_kernel<<<blocks, 256>>>(X1, X2);

    cudaFuncSetAttribute(cross_mma_kernel,
                         cudaFuncAttributeMaxDynamicSharedMemorySize, SMEM_TOTAL);
    dim3 grid(Tdim / BT, Mdim / BM, Ndim / BN);   // 16 x 16 x 16, t fastest
    cross_mma_kernel<<<grid, THREADS, SMEM_TOTAL>>>(Y);
}